// round 10
// baseline (speedup 1.0000x reference)
#include <cuda_runtime.h>
#include <cuda_bf16.h>
#include <cstdint>

// ============================================================================
// DeformableCurrents: e_ss - 2 e_st + e_tt
//   == sum over combined set (src ∪ tar) of K(c_p,c_q)*(w_p.w_q),
//   w = +normal (src), -normal (tar); f symmetric => triangular tiles.
//
// v10: batched inversion. All prior structural experiments (R2-R9) were
//   invariant at ~62-66us with exactly 8 MUFU rcp/warp-jj -> hypothesis:
//   MUFU is the binding pipe (effective rt ~14 cyc/SMSP). Montgomery
//   pairing halves MUFU: rp = rcp(d0*d1); r0 = rp*d1; r1 = rp*d0.
//   Keeps R9's g-vector loop (sum_j wj*r) + cross-iteration pipelining.
// ============================================================================

#define THREADS   256
#define NCH       4                  // packed chains per thread
#define IPT       (2 * NCH)          // 8 i-points per thread
#define ICHUNK    (THREADS * IPT)    // 2048
#define TJ        256                // j-subtile (== smem tile)
#define JSUB      (ICHUNK / TJ)      // 8

typedef unsigned long long u64;

__device__ double g_partials[1024];
__device__ unsigned int g_done = 0;

// ---- packed f32x2 helpers ---------------------------------------------------
__device__ __forceinline__ u64 fma2(u64 a, u64 b, u64 c) {
    u64 d; asm("fma.rn.f32x2 %0, %1, %2, %3;" : "=l"(d) : "l"(a), "l"(b), "l"(c));
    return d;
}
__device__ __forceinline__ u64 add2(u64 a, u64 b) {
    u64 d; asm("add.rn.f32x2 %0, %1, %2;" : "=l"(d) : "l"(a), "l"(b));
    return d;
}
__device__ __forceinline__ u64 mul2(u64 a, u64 b) {
    u64 d; asm("mul.rn.f32x2 %0, %1, %2;" : "=l"(d) : "l"(a), "l"(b));
    return d;
}
__device__ __forceinline__ u64 pack2(float lo, float hi) {
    u64 d; asm("mov.b64 %0, {%1, %2};" : "=l"(d) : "f"(lo), "f"(hi));
    return d;
}
__device__ __forceinline__ void unpack2(u64 p, float& lo, float& hi) {
    asm("mov.b64 {%0, %1}, %2;" : "=f"(lo), "=f"(hi) : "l"(p));
}
__device__ __forceinline__ float rcpf(float x) {
    float r; asm("rcp.approx.ftz.f32 %0, %1;" : "=f"(r) : "f"(x));
    return r;
}

// ---- per-point prep (center c, squared-norm a2, weight w) --------------------
__device__ __forceinline__ void make_point(
    int t, int N, int M,
    const float* __restrict__ verts, const float* __restrict__ tnorm,
    const float* __restrict__ tcent, const int* __restrict__ sidx,
    float& cx, float& cy, float& cz, float& a2,
    float& wx, float& wy, float& wz)
{
    cx = 0.f; cy = 0.f; cz = 0.f;
    wx = 0.f; wy = 0.f; wz = 0.f;
    if (t < N) {
        int i0 = sidx[3 * t + 0];
        int i1 = sidx[3 * t + 1];
        int i2 = sidx[3 * t + 2];
        float ax = verts[3 * i0], ay = verts[3 * i0 + 1], az = verts[3 * i0 + 2];
        float bx = verts[3 * i1], by = verts[3 * i1 + 1], bz = verts[3 * i1 + 2];
        float gx = verts[3 * i2], gy = verts[3 * i2 + 1], gz = verts[3 * i2 + 2];
        float e1x = ax - bx, e1y = ay - by, e1z = az - bz;
        float e2x = gx - bx, e2y = gy - by, e2z = gz - bz;
        wx = 0.5f * (e1y * e2z - e1z * e2y);
        wy = 0.5f * (e1z * e2x - e1x * e2z);
        wz = 0.5f * (e1x * e2y - e1y * e2x);
        cx = (ax + bx + gx) * (1.0f / 3.0f);
        cy = (ay + by + gy) * (1.0f / 3.0f);
        cz = (az + bz + gz) * (1.0f / 3.0f);
    } else if (t < N + M) {
        int j = t - N;
        cx = tcent[3 * j];  cy = tcent[3 * j + 1];  cz = tcent[3 * j + 2];
        wx = -tnorm[3 * j]; wy = -tnorm[3 * j + 1]; wz = -tnorm[3 * j + 2];
    }
    // padding: w = 0 -> zero contribution (denom >= 1, rcp safe)
    a2 = cx * cx + cy * cy + cz * cz;
}

// ----------------------------------------------------------------------------
__global__ __launch_bounds__(THREADS, 2)
void fused_kernel(const float* __restrict__ verts,
                  const float* __restrict__ tnorm,
                  const float* __restrict__ tcent,
                  const int*   __restrict__ sidx,
                  int N, int M, int T, int nBlocks,
                  float* __restrict__ out)
{
    // splatted j-subtile: 8 u64 per j (7 used + 1 pad) = 16 KB
    __shared__ __align__(16) u64 sj[TJ * 8];
    __shared__ double rbuf[THREADS];
    __shared__ int s_last;

    const int tid = threadIdx.x;

    // block -> (triangular tile-pair, j-subtile)
    int unit = blockIdx.x / JSUB;
    const int sub = blockIdx.x % JSUB;
    int ti = 0, row = T;
    while (unit >= row) { unit -= row; ti++; row--; }
    const int tj = ti + unit;
    const float scale = (ti == tj) ? 1.0f : 2.0f;

    const int ibase = ti * ICHUNK;
    const int jt    = tj * ICHUNK + sub * TJ;

    // ---- j prep + splat fill (1 j per thread) ----
    {
        int j = jt + tid;
        float cx, cy, cz, a2, wx, wy, wz;
        make_point(j, N, M, verts, tnorm, tcent, sidx, cx, cy, cz, a2, wx, wy, wz);
        u64* s = &sj[tid * 8];
        s[0] = pack2(-2.f * cx, -2.f * cx);
        s[1] = pack2(-2.f * cy, -2.f * cy);
        s[2] = pack2(-2.f * cz, -2.f * cz);
        s[3] = pack2(1.f + a2, 1.f + a2);
        s[4] = pack2(wx, wx);
        s[5] = pack2(wy, wy);
        s[6] = pack2(wz, wz);
    }

    // ---- i prep: only centers + a2 needed in the loop ----
    u64 pcx[NCH], pcy[NCH], pcz[NCH], pa2[NCH];
    u64 g0[NCH], g1[NCH], g2[NCH];        // g-vector accumulators
#pragma unroll
    for (int c = 0; c < NCH; c++) {
        float cxA, cyA, czA, a2A, wxA, wyA, wzA;
        float cxB, cyB, czB, a2B, wxB, wyB, wzB;
        int iA = ibase + (2 * c + 0) * THREADS + tid;
        int iB = ibase + (2 * c + 1) * THREADS + tid;
        make_point(iA, N, M, verts, tnorm, tcent, sidx, cxA, cyA, czA, a2A, wxA, wyA, wzA);
        make_point(iB, N, M, verts, tnorm, tcent, sidx, cxB, cyB, czB, a2B, wxB, wyB, wzB);
        pcx[c] = pack2(cxA, cxB);
        pcy[c] = pack2(cyA, cyB);
        pcz[c] = pack2(czA, czB);
        pa2[c] = pack2(a2A, a2B);
        g0[c] = 0ull; g1[c] = 0ull; g2[c] = 0ull;
    }

    __syncthreads();

    // ---- main pair loop: denom -> paired rcp -> g += wj * r (next iter) ----
    u64 rprev[NCH];
    u64 w0p = 0ull, w1p = 0ull, w2p = 0ull;   // previous iteration's splatted wj
#pragma unroll
    for (int c = 0; c < NCH; c++) rprev[c] = 0ull;

#pragma unroll 8
    for (int jj = 0; jj < TJ; jj++) {
        const ulonglong2* jp = (const ulonglong2*)&sj[jj * 8];
        const ulonglong2 v0 = jp[0];   // {-2cx, -2cy}
        const ulonglong2 v1 = jp[1];   // {-2cz, b}
        const ulonglong2 v2 = jp[2];   // {wx, wy}
        const ulonglong2 v3 = jp[3];   // {wz, pad}

        // denominators for THIS iteration (16 fma2)
        u64 d[NCH];
#pragma unroll
        for (int c = 0; c < NCH; c++) {
            u64 t = add2(pa2[c], v1.y);          // a_i + b_j
            t = fma2(v0.x, pcx[c], t);
            t = fma2(v0.y, pcy[c], t);
            d[c] = fma2(v1.x, pcz[c], t);        // = 1 + |ci-cj|^2
        }
        // g-updates from PREVIOUS iteration (12 fma2; operands long ready)
#pragma unroll
        for (int c = 0; c < NCH; c++) {
            g0[c] = fma2(w0p, rprev[c], g0[c]);
            g1[c] = fma2(w1p, rprev[c], g1[c]);
            g2[c] = fma2(w2p, rprev[c], g2[c]);
        }
        // reciprocals via batched inversion: 4 MUFU instead of 8.
        //   rp = rcp(d[c]*d[c+1]);  r[c] = rp*d[c+1];  r[c+1] = rp*d[c]
#pragma unroll
        for (int c = 0; c < NCH; c += 2) {
            u64 p = mul2(d[c], d[c + 1]);
            float p0, p1; unpack2(p, p0, p1);
            u64 rp = pack2(rcpf(p0), rcpf(p1));
            rprev[c]     = mul2(rp, d[c + 1]);
            rprev[c + 1] = mul2(rp, d[c]);
        }
        w0p = v2.x; w1p = v2.y; w2p = v3.x;
    }
    // drain the pipeline
#pragma unroll
    for (int c = 0; c < NCH; c++) {
        g0[c] = fma2(w0p, rprev[c], g0[c]);
        g1[c] = fma2(w1p, rprev[c], g1[c]);
        g2[c] = fma2(w2p, rprev[c], g2[c]);
    }

    // ---- final per-thread dot: e = sum_c wi_c . g_c (recompute wi) ----
    double s = 0.0;
#pragma unroll
    for (int c = 0; c < NCH; c++) {
        float cxA, cyA, czA, a2A, wxA, wyA, wzA;
        float cxB, cyB, czB, a2B, wxB, wyB, wzB;
        int iA = ibase + (2 * c + 0) * THREADS + tid;
        int iB = ibase + (2 * c + 1) * THREADS + tid;
        make_point(iA, N, M, verts, tnorm, tcent, sidx, cxA, cyA, czA, a2A, wxA, wyA, wzA);
        make_point(iB, N, M, verts, tnorm, tcent, sidx, cxB, cyB, czB, a2B, wxB, wyB, wzB);
        float g0A, g0B, g1A, g1B, g2A, g2B;
        unpack2(g0[c], g0A, g0B);
        unpack2(g1[c], g1A, g1B);
        unpack2(g2[c], g2A, g2B);
        float eA = wxA * g0A + wyA * g1A + wzA * g2A;
        float eB = wxB * g0B + wyB * g1B + wzB * g2B;
        s += (double)eA + (double)eB;
    }
    s *= (double)scale;

    // ---- deterministic block reduction (double) ----
    rbuf[tid] = s;
    __syncthreads();
#pragma unroll
    for (int off = THREADS / 2; off > 0; off >>= 1) {
        if (tid < off) rbuf[tid] += rbuf[tid + off];
        __syncthreads();
    }
    if (tid == 0) {
        g_partials[blockIdx.x] = rbuf[0];
        __threadfence();
        unsigned int ticket = atomicAdd(&g_done, 1u);
        s_last = (ticket == (unsigned int)(nBlocks - 1)) ? 1 : 0;
    }
    __syncthreads();

    // ---- last block: fixed-order deterministic final reduction ----
    if (s_last) {
        double fs = 0.0;
        for (int k = tid; k < nBlocks; k += THREADS)   // fixed assignment+order
            fs += g_partials[k];
        rbuf[tid] = fs;
        __syncthreads();
#pragma unroll
        for (int off = THREADS / 2; off > 0; off >>= 1) {
            if (tid < off) rbuf[tid] += rbuf[tid + off];
            __syncthreads();
        }
        if (tid == 0) {
            out[0] = (float)rbuf[0];
            g_done = 0;   // self-restore for next graph replay
        }
    }
}

// ----------------------------------------------------------------------------
extern "C" void kernel_launch(void* const* d_in, const int* in_sizes, int n_in,
                              void* d_out, int out_size)
{
    const float* verts = (const float*)d_in[0];   // src_vertices  (V,3)
    const float* tnorm = (const float*)d_in[1];   // tar_normals   (M,3)
    const float* tcent = (const float*)d_in[2];   // tar_centers   (M,3)
    const int*   sidx  = (const int*)  d_in[3];   // src_indices   (N,3)

    const int N = in_sizes[3] / 3;
    const int M = in_sizes[1] / 3;
    const int total = N + M;
    const int total_pad = ((total + ICHUNK - 1) / ICHUNK) * ICHUNK;
    const int T = total_pad / ICHUNK;             // 8 for 16384 points

    const int nBlocks = (T * (T + 1) / 2) * JSUB;   // 36 * 8 = 288
    fused_kernel<<<nBlocks, THREADS>>>(verts, tnorm, tcent, sidx,
                                       N, M, T, nBlocks, (float*)d_out);
}

// round 12
// speedup vs baseline: 1.2957x; 1.2957x over previous
#include <cuda_runtime.h>
#include <cuda_bf16.h>
#include <cstdint>

// ============================================================================
// DeformableCurrents: E = sum_{p,q} (w_p.w_q) / (1 + |c_p - c_q|^2)
// over combined src/tar set; f symmetric => triangular tiles (x2 off-diag).
//
// v12: denominator GEMM on tensor cores via mma.sync.m16n8k16.bf16 (plain
//   sm_80 PTX -- sm_103a-suffix tcgen05 is rejected by this toolchain).
//   Split-bf16 K=16 features give D = 1 + d2 exactly enough (~3e-4 abs):
//     A_i = [-2hx,-2hy,-2hz, -2lx,-2ly,-2lz, -2hx,-2hy,-2hz, ah,al, 1,1, 0,0,0]
//     B_j = [ hx,  hy,  hz,   hx,  hy,  hz,   lx,  ly,  lz,  1, 1, bh,bl,0,0,0]
//   Epilogue per element: rcp + 3-fma g-vector (weights stay fp32).
//   fp32 pipe load drops 7 -> 3 fma/pair; MUFU becomes the floor (~57k cyc).
// ============================================================================

typedef unsigned int u32;

#define THREADS 256
#define G       256          // square tile edge (points)
#define MAX_PTS 20480

__device__ u32    g_FA[8 * MAX_PTS];   // A features: 8 u32 (bf16x2) per point
__device__ u32    g_FB[8 * MAX_PTS];   // B features
__device__ float4 g_W[MAX_PTS];        // weights
__device__ double g_partials[4096];
__device__ unsigned int g_done = 0;

__device__ __forceinline__ float rcpf(float x) {
    float r; asm("rcp.approx.ftz.f32 %0, %1;" : "=f"(r) : "f"(x));
    return r;
}

// D(16x8,f32) = A(16x16,bf16) * B(16x8,bf16) + C
__device__ __forceinline__ void mma_bf16(
    float& c0, float& c1, float& c2, float& c3,
    u32 a0, u32 a1, u32 a2, u32 a3, u32 b0, u32 b1)
{
    float z = 0.f;
    asm volatile(
        "mma.sync.aligned.m16n8k16.row.col.f32.bf16.bf16.f32 "
        "{%0,%1,%2,%3}, {%4,%5,%6,%7}, {%8,%9}, {%10,%11,%12,%13};"
        : "=f"(c0), "=f"(c1), "=f"(c2), "=f"(c3)
        : "r"(a0), "r"(a1), "r"(a2), "r"(a3), "r"(b0), "r"(b1),
          "f"(z), "f"(z), "f"(z), "f"(z));
}

// ---- per-point geometry ------------------------------------------------------
__device__ __forceinline__ void make_point(
    int t, int N, int M,
    const float* __restrict__ verts, const float* __restrict__ tnorm,
    const float* __restrict__ tcent, const int* __restrict__ sidx,
    float& cx, float& cy, float& cz, float& a2,
    float& wx, float& wy, float& wz)
{
    cx = 0.f; cy = 0.f; cz = 0.f; wx = 0.f; wy = 0.f; wz = 0.f;
    if (t < N) {
        int i0 = sidx[3 * t + 0], i1 = sidx[3 * t + 1], i2 = sidx[3 * t + 2];
        float ax = verts[3 * i0], ay = verts[3 * i0 + 1], az = verts[3 * i0 + 2];
        float bx = verts[3 * i1], by = verts[3 * i1 + 1], bz = verts[3 * i1 + 2];
        float gx = verts[3 * i2], gy = verts[3 * i2 + 1], gz = verts[3 * i2 + 2];
        float e1x = ax - bx, e1y = ay - by, e1z = az - bz;
        float e2x = gx - bx, e2y = gy - by, e2z = gz - bz;
        wx = 0.5f * (e1y * e2z - e1z * e2y);
        wy = 0.5f * (e1z * e2x - e1x * e2z);
        wz = 0.5f * (e1x * e2y - e1y * e2x);
        cx = (ax + bx + gx) * (1.0f / 3.0f);
        cy = (ay + by + gy) * (1.0f / 3.0f);
        cz = (az + bz + gz) * (1.0f / 3.0f);
    } else if (t < N + M) {
        int j = t - N;
        cx = tcent[3 * j];  cy = tcent[3 * j + 1];  cz = tcent[3 * j + 2];
        wx = -tnorm[3 * j]; wy = -tnorm[3 * j + 1]; wz = -tnorm[3 * j + 2];
    }
    a2 = cx * cx + cy * cy + cz * cz;
}

__device__ __forceinline__ unsigned short bfb(float x) {
    __nv_bfloat16 h = __float2bfloat16(x);
    return *(unsigned short*)&h;
}
__device__ __forceinline__ float bff(unsigned short b) {
    __nv_bfloat16 h = *(__nv_bfloat16*)&b;
    return __bfloat162float(h);
}
__device__ __forceinline__ u32 pk(unsigned short lo, unsigned short hi) {
    return (u32)lo | ((u32)hi << 16);
}

// ---- prep: split-bf16 feature vectors + weights --------------------------------
__global__ void prep_kernel(const float* __restrict__ verts,
                            const float* __restrict__ tnorm,
                            const float* __restrict__ tcent,
                            const int*   __restrict__ sidx,
                            int N, int M, int total_pad)
{
    int p = blockIdx.x * blockDim.x + threadIdx.x;
    if (p >= total_pad) return;
    float cx, cy, cz, a2, wx, wy, wz;
    make_point(p, N, M, verts, tnorm, tcent, sidx, cx, cy, cz, a2, wx, wy, wz);

    unsigned short hx = bfb(cx), hy = bfb(cy), hz = bfb(cz);
    float hxf = bff(hx), hyf = bff(hy), hzf = bff(hz);
    unsigned short lx = bfb(cx - hxf), ly = bfb(cy - hyf), lz = bfb(cz - hzf);
    unsigned short m2hx = bfb(-2.f * hxf), m2hy = bfb(-2.f * hyf), m2hz = bfb(-2.f * hzf);
    unsigned short m2lx = bfb(-2.f * bff(lx)), m2ly = bfb(-2.f * bff(ly)), m2lz = bfb(-2.f * bff(lz));
    unsigned short ah = bfb(a2), al = bfb(a2 - bff(ah));
    float b = 1.f + a2;
    unsigned short bh = bfb(b), bl = bfb(b - bff(bh));
    unsigned short one = bfb(1.f), zz = 0;

    u32* A = &g_FA[8 * p];
    A[0] = pk(m2hx, m2hy); A[1] = pk(m2hz, m2lx);
    A[2] = pk(m2ly, m2lz); A[3] = pk(m2hx, m2hy);
    A[4] = pk(m2hz, ah);   A[5] = pk(al, one);
    A[6] = pk(one, zz);    A[7] = 0;

    u32* B = &g_FB[8 * p];
    B[0] = pk(hx, hy);  B[1] = pk(hz, hx);
    B[2] = pk(hy, hz);  B[3] = pk(lx, ly);
    B[4] = pk(lz, one); B[5] = pk(one, bh);
    B[6] = pk(bl, zz);  B[7] = 0;

    g_W[p] = make_float4(wx, wy, wz, 0.f);
}

// ---- main kernel: 256x256 triangular tiles, HMMA denominators ------------------
__global__ __launch_bounds__(THREADS)
void mma_kernel(int T, int nBlocks, float* __restrict__ out)
{
    __shared__ u32    sFB[G * 8];     // 8 KB: B features for the j-tile
    __shared__ float4 sWj[G];         // 4 KB
    __shared__ float4 sWi[G];         // 4 KB
    __shared__ double rbuf[THREADS];  // 2 KB
    __shared__ int s_last;

    const int tid = threadIdx.x;
    const int wid = tid >> 5;
    const int lid = tid & 31;
    const int gid = lid >> 2;     // groupID 0..7
    const int tig = lid & 3;      // thread-in-group 0..3

    // block -> (ti, tj) triangular
    int b = blockIdx.x, ti = 0, row = T;
    while (b >= row) { b -= row; ti++; row--; }
    const int tj = ti + b;
    const double scale = (ti == tj) ? 1.0 : 2.0;
    const int Ibase = ti * G;
    const int Jbase = tj * G;

    // stage j-tile: B features + weights; i weights
    for (int k = tid; k < G * 8; k += THREADS) sFB[k] = g_FB[Jbase * 8 + k];
    if (tid < G) { } // (G==THREADS)
    sWj[tid] = g_W[Jbase + tid];
    sWi[tid] = g_W[Ibase + tid];
    __syncthreads();

    // A fragments for this warp's two 16-row i-strips
    u32 a[2][4];
#pragma unroll
    for (int s = 0; s < 2; s++) {
        int r0 = Ibase + s * 128 + wid * 16 + gid;
        int r1 = r0 + 8;
        a[s][0] = g_FA[r0 * 8 + tig];
        a[s][1] = g_FA[r1 * 8 + tig];
        a[s][2] = g_FA[r0 * 8 + tig + 4];
        a[s][3] = g_FA[r1 * 8 + tig + 4];
    }

    // g-vector accumulators: [strip][row-half] x (x,y,z)
    float g00x = 0.f, g00y = 0.f, g00z = 0.f, g01x = 0.f, g01y = 0.f, g01z = 0.f;
    float g10x = 0.f, g10y = 0.f, g10z = 0.f, g11x = 0.f, g11y = 0.f, g11z = 0.f;

#pragma unroll 4
    for (int jt = 0; jt < G / 8; jt++) {           // 32 j-subtiles of 8 cols
        const u32 b0 = sFB[jt * 64 + gid * 8 + tig];
        const u32 b1 = sFB[jt * 64 + gid * 8 + tig + 4];
        const int n0 = jt * 8 + 2 * tig;
        const float4 wj0 = sWj[n0];
        const float4 wj1 = sWj[n0 + 1];

        // strip 0
        {
            float c0, c1, c2, c3;
            mma_bf16(c0, c1, c2, c3, a[0][0], a[0][1], a[0][2], a[0][3], b0, b1);
            float r00 = rcpf(c0), r01 = rcpf(c1), r10 = rcpf(c2), r11 = rcpf(c3);
            g00x = fmaf(wj0.x, r00, g00x); g00x = fmaf(wj1.x, r01, g00x);
            g00y = fmaf(wj0.y, r00, g00y); g00y = fmaf(wj1.y, r01, g00y);
            g00z = fmaf(wj0.z, r00, g00z); g00z = fmaf(wj1.z, r01, g00z);
            g01x = fmaf(wj0.x, r10, g01x); g01x = fmaf(wj1.x, r11, g01x);
            g01y = fmaf(wj0.y, r10, g01y); g01y = fmaf(wj1.y, r11, g01y);
            g01z = fmaf(wj0.z, r10, g01z); g01z = fmaf(wj1.z, r11, g01z);
        }
        // strip 1
        {
            float c0, c1, c2, c3;
            mma_bf16(c0, c1, c2, c3, a[1][0], a[1][1], a[1][2], a[1][3], b0, b1);
            float r00 = rcpf(c0), r01 = rcpf(c1), r10 = rcpf(c2), r11 = rcpf(c3);
            g10x = fmaf(wj0.x, r00, g10x); g10x = fmaf(wj1.x, r01, g10x);
            g10y = fmaf(wj0.y, r00, g10y); g10y = fmaf(wj1.y, r01, g10y);
            g10z = fmaf(wj0.z, r00, g10z); g10z = fmaf(wj1.z, r01, g10z);
            g11x = fmaf(wj0.x, r10, g11x); g11x = fmaf(wj1.x, r11, g11x);
            g11y = fmaf(wj0.y, r10, g11y); g11y = fmaf(wj1.y, r11, g11y);
            g11z = fmaf(wj0.z, r10, g11z); g11z = fmaf(wj1.z, r11, g11z);
        }
    }

    // final dot with i-weights
    double e = 0.0;
    {
        int r = wid * 16 + gid;            // strip 0 rows
        float4 wiA = sWi[r], wiB = sWi[r + 8];
        e += (double)(wiA.x * g00x + wiA.y * g00y + wiA.z * g00z);
        e += (double)(wiB.x * g01x + wiB.y * g01y + wiB.z * g01z);
        r += 128;                          // strip 1 rows
        float4 wiC = sWi[r], wiD = sWi[r + 8];
        e += (double)(wiC.x * g10x + wiC.y * g10y + wiC.z * g10z);
        e += (double)(wiD.x * g11x + wiD.y * g11y + wiD.z * g11z);
    }

    // deterministic block reduction
    rbuf[tid] = e * scale;
    __syncthreads();
#pragma unroll
    for (int off = THREADS / 2; off > 0; off >>= 1) {
        if (tid < off) rbuf[tid] += rbuf[tid + off];
        __syncthreads();
    }
    if (tid == 0) {
        g_partials[blockIdx.x] = rbuf[0];
        __threadfence();
        unsigned int ticket = atomicAdd(&g_done, 1u);
        s_last = (ticket == (unsigned int)(nBlocks - 1)) ? 1 : 0;
    }
    __syncthreads();

    // last block: fixed-order deterministic final reduction
    if (s_last) {
        double fs = 0.0;
        for (int k = tid; k < nBlocks; k += THREADS)
            fs += g_partials[k];
        rbuf[tid] = fs;
        __syncthreads();
#pragma unroll
        for (int off = THREADS / 2; off > 0; off >>= 1) {
            if (tid < off) rbuf[tid] += rbuf[tid + off];
            __syncthreads();
        }
        if (tid == 0) {
            out[0] = (float)rbuf[0];
            g_done = 0;   // self-restore for next graph replay
        }
    }
}

// ----------------------------------------------------------------------------
extern "C" void kernel_launch(void* const* d_in, const int* in_sizes, int n_in,
                              void* d_out, int out_size)
{
    const float* verts = (const float*)d_in[0];   // src_vertices  (V,3)
    const float* tnorm = (const float*)d_in[1];   // tar_normals   (M,3)
    const float* tcent = (const float*)d_in[2];   // tar_centers   (M,3)
    const int*   sidx  = (const int*)  d_in[3];   // src_indices   (N,3)

    const int N = in_sizes[3] / 3;
    const int M = in_sizes[1] / 3;
    const int total = N + M;
    const int total_pad = ((total + G - 1) / G) * G;
    const int T = total_pad / G;                  // 64 for 16384 points

    prep_kernel<<<(total_pad + 255) / 256, 256>>>(verts, tnorm, tcent, sidx,
                                                  N, M, total_pad);

    const int nBlocks = T * (T + 1) / 2;          // 2080
    mma_kernel<<<nBlocks, THREADS>>>(T, nBlocks, (float*)d_out);
}